// round 1
// baseline (speedup 1.0000x reference)
#include <cuda_runtime.h>
#include <cstdint>
#include <math.h>

// Problem dims (fixed by the dataset)
#define N_TOK 8192
#define DIM   1024

// Scratch: Q, K, V (32 MB each) + scores (256 MB). __device__ globals are the
// allowed allocation-free scratch mechanism.
__device__ float g_q[(size_t)N_TOK * DIM];
__device__ float g_k[(size_t)N_TOK * DIM];
__device__ float g_v[(size_t)N_TOK * DIM];
__device__ float g_s[(size_t)N_TOK * N_TOK];

using ull = unsigned long long;

// ---- packed fp32x2 helpers (sm_103a FFMA2 path; 2x fp32 throughput) ----
__device__ __forceinline__ ull pack2_dup(float x) {
    ull r;
    asm("mov.b64 %0, {%1, %1};" : "=l"(r) : "f"(x));
    return r;
}
__device__ __forceinline__ void fma2(ull& c, ull a, ull b) {
    asm("fma.rn.f32x2 %0, %1, %2, %0;" : "+l"(c) : "l"(a), "l"(b));
}
__device__ __forceinline__ float2 unpack2(ull c) {
    float2 f;
    asm("mov.b64 {%0, %1}, %2;" : "=f"(f.x), "=f"(f.y) : "l"(c));
    return f;
}

// ============================================================================
// GEMM NT:  C[m,n] = sum_k A[m,k] * B[n,k]  (+ bias[n] if bias != nullptr)
//   A: [M,K] row-major (lda=K), B: [N,K] row-major (ldb=K), C: [M,N] (ldc=N)
// Tile: 128x128x16, 256 threads, 8x8 micro-tile per thread, FFMA2 inner loop.
// Requires M%128==0, N%128==0, K%16==0 (true for all uses here).
// ============================================================================
__global__ __launch_bounds__(256, 2)
void gemm_nt(const float* __restrict__ A, const float* __restrict__ B,
             const float* __restrict__ bias, float* __restrict__ C,
             int M, int N, int K)
{
    __shared__ float As[16][128];
    __shared__ float Bs[16][128];

    const int m0 = blockIdx.y * 128;
    const int n0 = blockIdx.x * 128;
    const int t  = threadIdx.x;
    const int tx = t & 15;   // n-group
    const int ty = t >> 4;   // m-group

    ull acc[8][4];
#pragma unroll
    for (int i = 0; i < 8; i++)
#pragma unroll
        for (int j = 0; j < 4; j++) acc[i][j] = 0ULL;

    const int r0 = t >> 2;          // row 0..63 (second half +64)
    const int c4 = (t & 3) * 4;     // k offset within tile: 0,4,8,12

    for (int kt = 0; kt < K; kt += 16) {
#pragma unroll
        for (int h = 0; h < 2; h++) {
            const int r = r0 + h * 64;
            float4 va = *(const float4*)(A + (size_t)(m0 + r) * K + kt + c4);
            As[c4 + 0][r] = va.x; As[c4 + 1][r] = va.y;
            As[c4 + 2][r] = va.z; As[c4 + 3][r] = va.w;
            float4 vb = *(const float4*)(B + (size_t)(n0 + r) * K + kt + c4);
            Bs[c4 + 0][r] = vb.x; Bs[c4 + 1][r] = vb.y;
            Bs[c4 + 2][r] = vb.z; Bs[c4 + 3][r] = vb.w;
        }
        __syncthreads();

#pragma unroll
        for (int k = 0; k < 16; k++) {
            const float4 a0 = *(const float4*)&As[k][ty * 8];
            const float4 a1 = *(const float4*)&As[k][ty * 8 + 4];
            const ulonglong2 bb0 = *(const ulonglong2*)&Bs[k][tx * 8];
            const ulonglong2 bb1 = *(const ulonglong2*)&Bs[k][tx * 8 + 4];
            ull b[4] = { bb0.x, bb0.y, bb1.x, bb1.y };
            float am[8] = { a0.x, a0.y, a0.z, a0.w, a1.x, a1.y, a1.z, a1.w };
#pragma unroll
            for (int m = 0; m < 8; m++) {
                const ull ap = pack2_dup(am[m]);
                fma2(acc[m][0], ap, b[0]);
                fma2(acc[m][1], ap, b[1]);
                fma2(acc[m][2], ap, b[2]);
                fma2(acc[m][3], ap, b[3]);
            }
        }
        __syncthreads();
    }

    float bv[8];
#pragma unroll
    for (int j = 0; j < 8; j++)
        bv[j] = bias ? bias[n0 + tx * 8 + j] : 0.0f;

#pragma unroll
    for (int m = 0; m < 8; m++) {
        const int cm = m0 + ty * 8 + m;
        const int cn = n0 + tx * 8;
        float2 o0 = unpack2(acc[m][0]);
        float2 o1 = unpack2(acc[m][1]);
        float2 o2 = unpack2(acc[m][2]);
        float2 o3 = unpack2(acc[m][3]);
        float4 w0 = make_float4(o0.x + bv[0], o0.y + bv[1], o1.x + bv[2], o1.y + bv[3]);
        float4 w1 = make_float4(o2.x + bv[4], o2.y + bv[5], o3.x + bv[6], o3.y + bv[7]);
        *(float4*)(C + (size_t)cm * N + cn)     = w0;
        *(float4*)(C + (size_t)cm * N + cn + 4) = w1;
    }
}

// ============================================================================
// GEMM NN:  C[m,n] = sum_k A[m,k] * B[k,n]
//   A: [M,K] row-major (lda=K), B: [K,N] row-major (ldb=N), C: [M,N]
// Same tiling as above; only the B tile load differs (no transpose needed).
// ============================================================================
__global__ __launch_bounds__(256, 2)
void gemm_nn(const float* __restrict__ A, const float* __restrict__ B,
             float* __restrict__ C, int M, int N, int K)
{
    __shared__ float As[16][128];
    __shared__ float Bs[16][128];

    const int m0 = blockIdx.y * 128;
    const int n0 = blockIdx.x * 128;
    const int t  = threadIdx.x;
    const int tx = t & 15;
    const int ty = t >> 4;

    ull acc[8][4];
#pragma unroll
    for (int i = 0; i < 8; i++)
#pragma unroll
        for (int j = 0; j < 4; j++) acc[i][j] = 0ULL;

    const int ra = t >> 2;          // A-load row 0..63
    const int ca = (t & 3) * 4;     // A-load k offset
    const int rb = t >> 5;          // B-load k-row 0..7 (second half +8)
    const int cb = (t & 31) * 4;    // B-load n offset

    for (int kt = 0; kt < K; kt += 16) {
#pragma unroll
        for (int h = 0; h < 2; h++) {
            const int r = ra + h * 64;
            float4 va = *(const float4*)(A + (size_t)(m0 + r) * K + kt + ca);
            As[ca + 0][r] = va.x; As[ca + 1][r] = va.y;
            As[ca + 2][r] = va.z; As[ca + 3][r] = va.w;
            const int kr = rb + h * 8;
            float4 vb = *(const float4*)(B + (size_t)(kt + kr) * N + n0 + cb);
            *(float4*)&Bs[kr][cb] = vb;
        }
        __syncthreads();

#pragma unroll
        for (int k = 0; k < 16; k++) {
            const float4 a0 = *(const float4*)&As[k][ty * 8];
            const float4 a1 = *(const float4*)&As[k][ty * 8 + 4];
            const ulonglong2 bb0 = *(const ulonglong2*)&Bs[k][tx * 8];
            const ulonglong2 bb1 = *(const ulonglong2*)&Bs[k][tx * 8 + 4];
            ull b[4] = { bb0.x, bb0.y, bb1.x, bb1.y };
            float am[8] = { a0.x, a0.y, a0.z, a0.w, a1.x, a1.y, a1.z, a1.w };
#pragma unroll
            for (int m = 0; m < 8; m++) {
                const ull ap = pack2_dup(am[m]);
                fma2(acc[m][0], ap, b[0]);
                fma2(acc[m][1], ap, b[1]);
                fma2(acc[m][2], ap, b[2]);
                fma2(acc[m][3], ap, b[3]);
            }
        }
        __syncthreads();
    }

#pragma unroll
    for (int m = 0; m < 8; m++) {
        const int cm = m0 + ty * 8 + m;
        const int cn = n0 + tx * 8;
        float2 o0 = unpack2(acc[m][0]);
        float2 o1 = unpack2(acc[m][1]);
        float2 o2 = unpack2(acc[m][2]);
        float2 o3 = unpack2(acc[m][3]);
        *(float4*)(C + (size_t)cm * N + cn)     = make_float4(o0.x, o0.y, o1.x, o1.y);
        *(float4*)(C + (size_t)cm * N + cn + 4) = make_float4(o2.x, o2.y, o3.x, o3.y);
    }
}

// ============================================================================
// Row softmax, in place. One block per row (8192 cols), 256 threads,
// 32 elements per thread held in registers.
// ============================================================================
__global__ __launch_bounds__(256)
void softmax_rows(float* __restrict__ S)
{
    const int row = blockIdx.x;
    float* p = S + (size_t)row * N_TOK;
    const int t = threadIdx.x;
    const int lane = t & 31;
    const int warp = t >> 5;

    __shared__ float red[10];   // [0..7] warp partials, [8] max, [9] sum

    float4 v[8];
    float mx = -INFINITY;
#pragma unroll
    for (int i = 0; i < 8; i++) {
        v[i] = *(const float4*)(p + (size_t)(i * 256 + t) * 4);
        mx = fmaxf(mx, fmaxf(fmaxf(v[i].x, v[i].y), fmaxf(v[i].z, v[i].w)));
    }
#pragma unroll
    for (int o = 16; o > 0; o >>= 1)
        mx = fmaxf(mx, __shfl_xor_sync(0xFFFFFFFFu, mx, o));
    if (lane == 0) red[warp] = mx;
    __syncthreads();
    if (t == 0) {
        float m = red[0];
#pragma unroll
        for (int w = 1; w < 8; w++) m = fmaxf(m, red[w]);
        red[8] = m;
    }
    __syncthreads();
    mx = red[8];

    float sum = 0.0f;
#pragma unroll
    for (int i = 0; i < 8; i++) {
        v[i].x = __expf(v[i].x - mx);
        v[i].y = __expf(v[i].y - mx);
        v[i].z = __expf(v[i].z - mx);
        v[i].w = __expf(v[i].w - mx);
        sum += (v[i].x + v[i].y) + (v[i].z + v[i].w);
    }
#pragma unroll
    for (int o = 16; o > 0; o >>= 1)
        sum += __shfl_xor_sync(0xFFFFFFFFu, sum, o);
    if (lane == 0) red[warp] = sum;
    __syncthreads();
    if (t == 0) {
        float s = 0.0f;
#pragma unroll
        for (int w = 0; w < 8; w++) s += red[w];
        red[9] = s;
    }
    __syncthreads();
    const float inv = 1.0f / red[9];

#pragma unroll
    for (int i = 0; i < 8; i++) {
        v[i].x *= inv; v[i].y *= inv; v[i].z *= inv; v[i].w *= inv;
        *(float4*)(p + (size_t)(i * 256 + t) * 4) = v[i];
    }
}

// ============================================================================
// Launch: QKV (3x GEMM-NT + bias) -> S = Q K^T (GEMM-NT) -> softmax -> O = P V
// All plain kernel launches on the legacy stream: graph-capturable, alloc-free.
// ============================================================================
extern "C" void kernel_launch(void* const* d_in, const int* in_sizes, int n_in,
                              void* d_out, int out_size)
{
    const float* emb = (const float*)d_in[0];
    const float* Wq  = (const float*)d_in[1];
    const float* bq  = (const float*)d_in[2];
    const float* Wk  = (const float*)d_in[3];
    const float* bk  = (const float*)d_in[4];
    const float* Wv  = (const float*)d_in[5];
    const float* bv  = (const float*)d_in[6];
    float* out = (float*)d_out;

    float *q, *k, *v, *s;
    cudaGetSymbolAddress((void**)&q, g_q);
    cudaGetSymbolAddress((void**)&k, g_k);
    cudaGetSymbolAddress((void**)&v, g_v);
    cudaGetSymbolAddress((void**)&s, g_s);

    // QKV projections: [8192,1024] @ [1024,1024]^T + bias
    gemm_nt<<<dim3(DIM / 128, N_TOK / 128), 256>>>(emb, Wq, bq, q, N_TOK, DIM, DIM);
    gemm_nt<<<dim3(DIM / 128, N_TOK / 128), 256>>>(emb, Wk, bk, k, N_TOK, DIM, DIM);
    gemm_nt<<<dim3(DIM / 128, N_TOK / 128), 256>>>(emb, Wv, bv, v, N_TOK, DIM, DIM);

    // Scores: [8192,1024] @ [8192,1024]^T -> [8192,8192]
    gemm_nt<<<dim3(N_TOK / 128, N_TOK / 128), 256>>>(q, k, nullptr, s, N_TOK, N_TOK, DIM);

    // Row softmax in place
    softmax_rows<<<N_TOK, 256>>>(s);

    // Output: [8192,8192] @ [8192,1024] -> [8192,1024] (== [8192,1,1024])
    gemm_nn<<<dim3(DIM / 128, N_TOK / 128), 256>>>(s, v, out, N_TOK, DIM, N_TOK);
}